// round 1
// baseline (speedup 1.0000x reference)
#include <cuda_runtime.h>
#include <math.h>
#include <stdint.h>

// Problem constants
#define BB   4
#define SS   2048
#define HID  1024
#define NH   16
#define HD   64
#define MR   (BB*SS)   // 8192 rows

// Scratch (device globals; no allocations allowed)
__device__ float g_q [ (size_t)MR * HID ];
__device__ float g_kv[ (size_t)MR * 2 * HID ];
__device__ float g_ao[ (size_t)MR * HID ];

// ----------------------------------------------------------------------------
// GEMM: C[M,N] = A[M,K] * W[N,K]^T + bias[N]   (fp32, 128x128x16 tile)
// ----------------------------------------------------------------------------
__global__ __launch_bounds__(256)
void gemm_nt_bias(const float* __restrict__ A, const float* __restrict__ W,
                  const float* __restrict__ bias, float* __restrict__ C,
                  int M, int N, int K)
{
    __shared__ float As[16][132];
    __shared__ float Bs[16][132];

    const int tid = threadIdx.x;
    const int tx  = tid & 15;
    const int ty  = tid >> 4;
    const int row0 = blockIdx.y * 128;
    const int col0 = blockIdx.x * 128;

    float acc[8][8];
#pragma unroll
    for (int i = 0; i < 8; i++)
#pragma unroll
        for (int j = 0; j < 8; j++) acc[i][j] = 0.f;

    for (int k0 = 0; k0 < K; k0 += 16) {
        // Load A tile (128 x 16) as float4s
#pragma unroll
        for (int t = 0; t < 2; t++) {
            int idx = tid + t * 256;        // 0..511 float4s
            int mm  = idx >> 2;
            int k4  = (idx & 3) * 4;
            float4 v = *reinterpret_cast<const float4*>(
                &A[(size_t)(row0 + mm) * K + k0 + k4]);
            As[k4 + 0][mm] = v.x; As[k4 + 1][mm] = v.y;
            As[k4 + 2][mm] = v.z; As[k4 + 3][mm] = v.w;
        }
        // Load W tile (128 x 16) as float4s
#pragma unroll
        for (int t = 0; t < 2; t++) {
            int idx = tid + t * 256;
            int nn  = idx >> 2;
            int k4  = (idx & 3) * 4;
            float4 v = *reinterpret_cast<const float4*>(
                &W[(size_t)(col0 + nn) * K + k0 + k4]);
            Bs[k4 + 0][nn] = v.x; Bs[k4 + 1][nn] = v.y;
            Bs[k4 + 2][nn] = v.z; Bs[k4 + 3][nn] = v.w;
        }
        __syncthreads();

#pragma unroll
        for (int kk = 0; kk < 16; kk++) {
            float a[8], b[8];
#pragma unroll
            for (int i = 0; i < 8; i++) a[i] = As[kk][ty + i * 16];
#pragma unroll
            for (int j = 0; j < 8; j++) b[j] = Bs[kk][tx + j * 16];
#pragma unroll
            for (int i = 0; i < 8; i++)
#pragma unroll
                for (int j = 0; j < 8; j++)
                    acc[i][j] += a[i] * b[j];
        }
        __syncthreads();
    }

#pragma unroll
    for (int j = 0; j < 8; j++) {
        int col = col0 + tx + j * 16;
        float bv = bias ? bias[col] : 0.f;
#pragma unroll
        for (int i = 0; i < 8; i++) {
            int row = row0 + ty + i * 16;
            C[(size_t)row * N + col] = acc[i][j] + bv;
        }
    }
}

// ----------------------------------------------------------------------------
// QK norm: t / max(||t||, eps) * sqrt(D) * gamma    (one warp per row-head)
// ----------------------------------------------------------------------------
__global__ __launch_bounds__(256)
void qknorm_kernel(const float* __restrict__ gq, const float* __restrict__ gk)
{
    int warp = (blockIdx.x * blockDim.x + threadIdx.x) >> 5;
    int lane = threadIdx.x & 31;
    const int nq = MR * NH;

    float* base;
    const float* gamma;
    int stride;
    int t = warp;
    if (t < nq) { base = g_q;  gamma = gq; stride = HID; }
    else        { t -= nq; base = g_kv; gamma = gk; stride = 2 * HID; }

    int row = t >> 4;
    int h   = t & 15;
    float* p = base + (size_t)row * stride + h * HD;

    float2 v = *reinterpret_cast<float2*>(p + lane * 2);
    float ss = v.x * v.x + v.y * v.y;
#pragma unroll
    for (int m = 16; m > 0; m >>= 1)
        ss += __shfl_xor_sync(0xffffffffu, ss, m);
    float inv = 8.0f / fmaxf(sqrtf(ss), 1e-12f);   // sqrt(64) / max(norm, eps)
    float2 g = *reinterpret_cast<const float2*>(gamma + h * HD + lane * 2);
    v.x *= inv * g.x;
    v.y *= inv * g.y;
    *reinterpret_cast<float2*>(p + lane * 2) = v;
}

// ----------------------------------------------------------------------------
// Flash-style attention, fp32. Block = 64 queries x one (b,h), stream 64-key
// tiles with online softmax. 256 threads, 4x4 micro-tiles.
// ----------------------------------------------------------------------------
#define ATT_STRIDE 66
#define ATT_SMEM_FLOATS (4 * 64 * ATT_STRIDE)
#define ATT_SMEM_BYTES  (ATT_SMEM_FLOATS * 4)

__global__ __launch_bounds__(256)
void attn_kernel(const float* __restrict__ qg, const float* __restrict__ kvg,
                 float* __restrict__ og)
{
    extern __shared__ float smem[];
    float* Qs = smem;                         // [64][66]
    float* Ks = Qs + 64 * ATT_STRIDE;         // [64][66]
    float* Vs = Ks + 64 * ATT_STRIDE;         // [64][66]
    float* Ps = Vs + 64 * ATT_STRIDE;         // [64][66]

    const int tid = threadIdx.x;
    const int tx  = tid & 15;
    const int ty  = tid >> 4;
    const int bh  = blockIdx.y;
    const int b   = bh >> 4;
    const int h   = bh & 15;
    const int q0  = blockIdx.x * 64;

    const float* Qg = qg + ((size_t)(b * SS + q0)) * HID + h * HD;
    const float* Kg = kvg + (size_t)b * SS * (2 * HID) + h * HD;
    const float* Vg = Kg + HID;

    // Load Q tile [64 q][64 d]
#pragma unroll
    for (int t = 0; t < 16; t++) {
        int idx = tid + t * 256;
        int r = idx >> 6, c = idx & 63;
        Qs[r * ATT_STRIDE + c] = Qg[(size_t)r * HID + c];
    }

    float m_run[4], l_run[4], acc_o[4][4];
#pragma unroll
    for (int i = 0; i < 4; i++) {
        m_run[i] = -INFINITY;
        l_run[i] = 0.f;
#pragma unroll
        for (int j = 0; j < 4; j++) acc_o[i][j] = 0.f;
    }
    __syncthreads();

    for (int kt = 0; kt < SS; kt += 64) {
        // Load K,V tiles [64 k][64 d]
#pragma unroll
        for (int t = 0; t < 16; t++) {
            int idx = tid + t * 256;
            int r = idx >> 6, c = idx & 63;
            Ks[r * ATT_STRIDE + c] = Kg[(size_t)(kt + r) * (2 * HID) + c];
            Vs[r * ATT_STRIDE + c] = Vg[(size_t)(kt + r) * (2 * HID) + c];
        }
        __syncthreads();

        // S = Q K^T  (64x64, 4x4 per thread)
        float s[4][4];
#pragma unroll
        for (int i = 0; i < 4; i++)
#pragma unroll
            for (int j = 0; j < 4; j++) s[i][j] = 0.f;

#pragma unroll
        for (int d = 0; d < 64; d++) {
            float a[4], bb[4];
#pragma unroll
            for (int i = 0; i < 4; i++) a[i]  = Qs[(ty + i * 16) * ATT_STRIDE + d];
#pragma unroll
            for (int j = 0; j < 4; j++) bb[j] = Ks[(tx + j * 16) * ATT_STRIDE + d];
#pragma unroll
            for (int i = 0; i < 4; i++)
#pragma unroll
                for (int j = 0; j < 4; j++)
                    s[i][j] += a[i] * bb[j];
        }

        // Online softmax per query row (16-lane row groups)
#pragma unroll
        for (int i = 0; i < 4; i++) {
            float mx = s[i][0];
#pragma unroll
            for (int j = 1; j < 4; j++) mx = fmaxf(mx, s[i][j]);
#pragma unroll
            for (int m = 8; m > 0; m >>= 1)
                mx = fmaxf(mx, __shfl_xor_sync(0xffffffffu, mx, m));
            float m_new = fmaxf(m_run[i], mx);
            float corr  = __expf(m_run[i] - m_new);
            float psum  = 0.f;
#pragma unroll
            for (int j = 0; j < 4; j++) {
                s[i][j] = __expf(s[i][j] - m_new);
                psum += s[i][j];
            }
#pragma unroll
            for (int m = 8; m > 0; m >>= 1)
                psum += __shfl_xor_sync(0xffffffffu, psum, m);
            l_run[i] = l_run[i] * corr + psum;
            m_run[i] = m_new;
#pragma unroll
            for (int j = 0; j < 4; j++) acc_o[i][j] *= corr;
        }

        // Stage P
#pragma unroll
        for (int i = 0; i < 4; i++)
#pragma unroll
            for (int j = 0; j < 4; j++)
                Ps[(ty + i * 16) * ATT_STRIDE + (tx + j * 16)] = s[i][j];
        __syncthreads();

        // O += P V
#pragma unroll
        for (int kk = 0; kk < 64; kk++) {
            float a[4], bb[4];
#pragma unroll
            for (int i = 0; i < 4; i++) a[i]  = Ps[(ty + i * 16) * ATT_STRIDE + kk];
#pragma unroll
            for (int j = 0; j < 4; j++) bb[j] = Vs[kk * ATT_STRIDE + (tx + j * 16)];
#pragma unroll
            for (int i = 0; i < 4; i++)
#pragma unroll
                for (int j = 0; j < 4; j++)
                    acc_o[i][j] += a[i] * bb[j];
        }
        __syncthreads();
    }

    // Write O / l
#pragma unroll
    for (int i = 0; i < 4; i++) {
        int qr = ty + i * 16;
        float invl = 1.0f / l_run[i];
#pragma unroll
        for (int j = 0; j < 4; j++) {
            int dc = tx + j * 16;
            og[((size_t)(b * SS + q0 + qr)) * HID + h * HD + dc] = acc_o[i][j] * invl;
        }
    }
}

// ----------------------------------------------------------------------------
// Launch
// ----------------------------------------------------------------------------
extern "C" void kernel_launch(void* const* d_in, const int* in_sizes, int n_in,
                              void* d_out, int out_size)
{
    const float* x     = (const float*)d_in[0];
    const float* q_w   = (const float*)d_in[1];
    const float* q_b   = (const float*)d_in[2];
    const float* kv_w  = (const float*)d_in[3];
    const float* kv_b  = (const float*)d_in[4];
    const float* gq    = (const float*)d_in[5];
    const float* gk    = (const float*)d_in[6];
    const float* out_w = (const float*)d_in[7];
    float* out = (float*)d_out;

    float *pq, *pkv, *pao;
    cudaGetSymbolAddress((void**)&pq,  g_q);
    cudaGetSymbolAddress((void**)&pkv, g_kv);
    cudaGetSymbolAddress((void**)&pao, g_ao);

    // Q projection: [8192,1024] = x @ q_w^T + q_b
    {
        dim3 grid(HID / 128, MR / 128);
        gemm_nt_bias<<<grid, 256>>>(x, q_w, q_b, pq, MR, HID, HID);
    }
    // KV projection: [8192,2048] = x @ kv_w^T + kv_b
    {
        dim3 grid((2 * HID) / 128, MR / 128);
        gemm_nt_bias<<<grid, 256>>>(x, kv_w, kv_b, pkv, MR, 2 * HID, HID);
    }
    // QK norm (q in g_q, k = first half of g_kv)
    {
        int total_warps = 2 * MR * NH;         // 262144
        int blocks = total_warps / 8;           // 8 warps per 256-thread block
        qknorm_kernel<<<blocks, 256>>>(gq, gk);
    }
    // Attention
    {
        cudaFuncSetAttribute(attn_kernel,
                             cudaFuncAttributeMaxDynamicSharedMemorySize,
                             ATT_SMEM_BYTES);
        dim3 grid(SS / 64, BB * NH);            // (32, 64)
        attn_kernel<<<grid, 256, ATT_SMEM_BYTES>>>(pq, pkv, pao);
    }
    // Output projection: out = ao @ out_w^T
    {
        dim3 grid(HID / 128, MR / 128);
        gemm_nt_bias<<<grid, 256>>>(pao, out_w, nullptr, out, MR, HID, HID);
    }
}

// round 3
// speedup vs baseline: 1.5100x; 1.5100x over previous
#include <cuda_runtime.h>
#include <cuda_bf16.h>
#include <math.h>
#include <stdint.h>

// Problem constants
#define BB   4
#define SS   2048
#define HID  1024
#define NH   16
#define HD   64
#define MR   (BB*SS)   // 8192 rows

// Scratch (device globals; no allocations allowed)
__device__ float g_q [ (size_t)MR * HID ];
__device__ float g_kv[ (size_t)MR * 2 * HID ];
__device__ float g_ao[ (size_t)MR * HID ];

__device__ __forceinline__ uint32_t smem_u32(const void* p) {
    uint32_t a;
    asm("{ .reg .u64 t; cvta.to.shared.u64 t, %1; cvt.u32.u64 %0, t; }"
        : "=r"(a) : "l"(p));
    return a;
}

// ============================================================================
// 3xBF16 mma.sync GEMM: C[M,N] = A[M,K] @ W[N,K]^T + bias
// CTA 128x128 tile, 8 warps (each 64m x 32n), K chunked by 32.
// ============================================================================
#define KC    32
#define PITCH 40   // bf16 elements per smem row (80B -> conflict-free ldmatrix)

__device__ __forceinline__ void bf16_split2(float x, float y,
                                            uint32_t& hi, uint32_t& lo) {
    __nv_bfloat16 hx = __float2bfloat16(x);
    __nv_bfloat16 hy = __float2bfloat16(y);
    __nv_bfloat16 lx = __float2bfloat16(x - __bfloat162float(hx));
    __nv_bfloat16 ly = __float2bfloat16(y - __bfloat162float(hy));
    __nv_bfloat162 h; h.x = hx; h.y = hy;
    __nv_bfloat162 l; l.x = lx; l.y = ly;
    hi = *reinterpret_cast<uint32_t*>(&h);
    lo = *reinterpret_cast<uint32_t*>(&l);
}

#define LDM_X4(r0, r1, r2, r3, addr) \
    asm volatile("ldmatrix.sync.aligned.m8n8.x4.shared.b16 {%0,%1,%2,%3}, [%4];" \
                 : "=r"(r0), "=r"(r1), "=r"(r2), "=r"(r3) : "r"(addr))

#define MMA_BF16(d, a, b0v, b1v) \
    asm volatile("mma.sync.aligned.m16n8k16.row.col.f32.bf16.bf16.f32 " \
                 "{%0,%1,%2,%3}, {%4,%5,%6,%7}, {%8,%9}, {%0,%1,%2,%3};" \
                 : "+f"((d)[0]), "+f"((d)[1]), "+f"((d)[2]), "+f"((d)[3]) \
                 : "r"((a)[0]), "r"((a)[1]), "r"((a)[2]), "r"((a)[3]), \
                   "r"(b0v), "r"(b1v))

__global__ __launch_bounds__(256, 2)
void gemm_bf16x3(const float* __restrict__ A, const float* __restrict__ W,
                 const float* __restrict__ bias, float* __restrict__ C,
                 int M, int N, int K)
{
    __shared__ __align__(16) __nv_bfloat16 sAh[128 * PITCH];
    __shared__ __align__(16) __nv_bfloat16 sAl[128 * PITCH];
    __shared__ __align__(16) __nv_bfloat16 sBh[128 * PITCH];
    __shared__ __align__(16) __nv_bfloat16 sBl[128 * PITCH];

    const int tid  = threadIdx.x;
    const int wid  = tid >> 5;
    const int lane = tid & 31;
    const int row0 = blockIdx.y * 128;
    const int col0 = blockIdx.x * 128;
    const int wm   = (wid >> 2) * 64;   // warp row offset within CTA tile
    const int wn   = (wid & 3) * 32;    // warp col offset

    const uint32_t bAh = smem_u32(sAh);
    const uint32_t bAl = smem_u32(sAl);
    const uint32_t bBh = smem_u32(sBh);
    const uint32_t bBl = smem_u32(sBl);

    // per-lane ldmatrix addressing
    const int a_row = lane & 15;                      // row within 16-row A tile
    const int a_k   = (lane >> 4) << 3;               // +0 / +8 k offset
    const int b_n   = (lane & 7) + ((lane >> 4) << 3);// row within 16-row B tile pair
    const int b_k   = lane & 8;                       // +0 / +8 k offset

    float acc[4][4][4];
#pragma unroll
    for (int mt = 0; mt < 4; mt++)
#pragma unroll
        for (int nt = 0; nt < 4; nt++)
#pragma unroll
            for (int r = 0; r < 4; r++) acc[mt][nt][r] = 0.f;

    for (int k0 = 0; k0 < K; k0 += KC) {
        // ---- load + split A (128 x 32 fp32) and B (=W rows col0.., 128 x 32)
#pragma unroll
        for (int t = 0; t < 4; t++) {
            int idx = tid + t * 256;        // 0..1023 float4s
            int r   = idx >> 3;
            int c4  = (idx & 7) * 4;
            float4 v = *reinterpret_cast<const float4*>(
                &A[(size_t)(row0 + r) * K + k0 + c4]);
            uint32_t h0, l0, h1, l1;
            bf16_split2(v.x, v.y, h0, l0);
            bf16_split2(v.z, v.w, h1, l1);
            uint2 ph = make_uint2(h0, h1);
            uint2 pl = make_uint2(l0, l1);
            *reinterpret_cast<uint2*>(&sAh[r * PITCH + c4]) = ph;
            *reinterpret_cast<uint2*>(&sAl[r * PITCH + c4]) = pl;
        }
#pragma unroll
        for (int t = 0; t < 4; t++) {
            int idx = tid + t * 256;
            int r   = idx >> 3;
            int c4  = (idx & 7) * 4;
            float4 v = *reinterpret_cast<const float4*>(
                &W[(size_t)(col0 + r) * K + k0 + c4]);
            uint32_t h0, l0, h1, l1;
            bf16_split2(v.x, v.y, h0, l0);
            bf16_split2(v.z, v.w, h1, l1);
            uint2 ph = make_uint2(h0, h1);
            uint2 pl = make_uint2(l0, l1);
            *reinterpret_cast<uint2*>(&sBh[r * PITCH + c4]) = ph;
            *reinterpret_cast<uint2*>(&sBl[r * PITCH + c4]) = pl;
        }
        __syncthreads();

#pragma unroll
        for (int kk = 0; kk < KC; kk += 16) {
            // B fragments: 4 n-tiles (8 cols each), hi & lo
            uint32_t bh[8], bl[8];
#pragma unroll
            for (int p = 0; p < 2; p++) {
                uint32_t off = (uint32_t)((wn + p * 16 + b_n) * PITCH + kk + b_k) * 2u;
                LDM_X4(bh[p*4+0], bh[p*4+1], bh[p*4+2], bh[p*4+3], bBh + off);
                LDM_X4(bl[p*4+0], bl[p*4+1], bl[p*4+2], bl[p*4+3], bBl + off);
            }
#pragma unroll
            for (int mt = 0; mt < 4; mt++) {
                uint32_t ah[4], al[4];
                uint32_t off = (uint32_t)((wm + mt * 16 + a_row) * PITCH + kk + a_k) * 2u;
                LDM_X4(ah[0], ah[1], ah[2], ah[3], bAh + off);
                LDM_X4(al[0], al[1], al[2], al[3], bAl + off);
#pragma unroll
                for (int nt = 0; nt < 4; nt++) {
                    int p   = nt >> 1;
                    int o   = (nt & 1) * 2;
                    uint32_t b0h = bh[p*4 + o], b1h = bh[p*4 + o + 1];
                    uint32_t b0l = bl[p*4 + o], b1l = bl[p*4 + o + 1];
                    MMA_BF16(acc[mt][nt], ah, b0h, b1h);   // hi*hi
                    MMA_BF16(acc[mt][nt], ah, b0l, b1l);   // hi*lo
                    MMA_BF16(acc[mt][nt], al, b0h, b1h);   // lo*hi
                }
            }
        }
        __syncthreads();
    }

    // ---- epilogue: c frag (g,2t),(g,2t+1),(g+8,2t),(g+8,2t+1)
    const int g  = lane >> 2;
    const int t2 = (lane & 3) * 2;
#pragma unroll
    for (int mt = 0; mt < 4; mt++) {
#pragma unroll
        for (int nt = 0; nt < 4; nt++) {
            int row = row0 + wm + mt * 16 + g;
            int col = col0 + wn + nt * 8 + t2;
            float bv0 = bias ? __ldg(&bias[col])     : 0.f;
            float bv1 = bias ? __ldg(&bias[col + 1]) : 0.f;
            float2 v0 = make_float2(acc[mt][nt][0] + bv0, acc[mt][nt][1] + bv1);
            float2 v1 = make_float2(acc[mt][nt][2] + bv0, acc[mt][nt][3] + bv1);
            *reinterpret_cast<float2*>(&C[(size_t)row * N + col]) = v0;
            *reinterpret_cast<float2*>(&C[(size_t)(row + 8) * N + col]) = v1;
        }
    }
}

// ----------------------------------------------------------------------------
// QK norm: t / max(||t||, eps) * sqrt(D) * gamma    (one warp per row-head)
// ----------------------------------------------------------------------------
__global__ __launch_bounds__(256)
void qknorm_kernel(const float* __restrict__ gq, const float* __restrict__ gk)
{
    int warp = (blockIdx.x * blockDim.x + threadIdx.x) >> 5;
    int lane = threadIdx.x & 31;
    const int nq = MR * NH;

    float* base;
    const float* gamma;
    int stride;
    int t = warp;
    if (t < nq) { base = g_q;  gamma = gq; stride = HID; }
    else        { t -= nq; base = g_kv; gamma = gk; stride = 2 * HID; }

    int row = t >> 4;
    int h   = t & 15;
    float* p = base + (size_t)row * stride + h * HD;

    float2 v = *reinterpret_cast<float2*>(p + lane * 2);
    float ss = v.x * v.x + v.y * v.y;
#pragma unroll
    for (int m = 16; m > 0; m >>= 1)
        ss += __shfl_xor_sync(0xffffffffu, ss, m);
    float inv = 8.0f / fmaxf(sqrtf(ss), 1e-12f);
    float2 g = *reinterpret_cast<const float2*>(gamma + h * HD + lane * 2);
    v.x *= inv * g.x;
    v.y *= inv * g.y;
    *reinterpret_cast<float2*>(p + lane * 2) = v;
}

// ----------------------------------------------------------------------------
// Flash-style attention, fp32 SIMT (round-1 proven version)
// ----------------------------------------------------------------------------
#define ATT_STRIDE 66
#define ATT_SMEM_FLOATS (4 * 64 * ATT_STRIDE)
#define ATT_SMEM_BYTES  (ATT_SMEM_FLOATS * 4)

__global__ __launch_bounds__(256)
void attn_kernel(const float* __restrict__ qg, const float* __restrict__ kvg,
                 float* __restrict__ og)
{
    extern __shared__ float smemf[];
    float* Qs = smemf;
    float* Ks = Qs + 64 * ATT_STRIDE;
    float* Vs = Ks + 64 * ATT_STRIDE;
    float* Ps = Vs + 64 * ATT_STRIDE;

    const int tid = threadIdx.x;
    const int tx  = tid & 15;
    const int ty  = tid >> 4;
    const int bh  = blockIdx.y;
    const int b   = bh >> 4;
    const int h   = bh & 15;
    const int q0  = blockIdx.x * 64;

    const float* Qg = qg + ((size_t)(b * SS + q0)) * HID + h * HD;
    const float* Kg = kvg + (size_t)b * SS * (2 * HID) + h * HD;
    const float* Vg = Kg + HID;

#pragma unroll
    for (int t = 0; t < 16; t++) {
        int idx = tid + t * 256;
        int r = idx >> 6, c = idx & 63;
        Qs[r * ATT_STRIDE + c] = Qg[(size_t)r * HID + c];
    }

    float m_run[4], l_run[4], acc_o[4][4];
#pragma unroll
    for (int i = 0; i < 4; i++) {
        m_run[i] = -INFINITY;
        l_run[i] = 0.f;
#pragma unroll
        for (int j = 0; j < 4; j++) acc_o[i][j] = 0.f;
    }
    __syncthreads();

    for (int kt = 0; kt < SS; kt += 64) {
#pragma unroll
        for (int t = 0; t < 16; t++) {
            int idx = tid + t * 256;
            int r = idx >> 6, c = idx & 63;
            Ks[r * ATT_STRIDE + c] = Kg[(size_t)(kt + r) * (2 * HID) + c];
            Vs[r * ATT_STRIDE + c] = Vg[(size_t)(kt + r) * (2 * HID) + c];
        }
        __syncthreads();

        float s[4][4];
#pragma unroll
        for (int i = 0; i < 4; i++)
#pragma unroll
            for (int j = 0; j < 4; j++) s[i][j] = 0.f;

#pragma unroll
        for (int d = 0; d < 64; d++) {
            float a[4], bb[4];
#pragma unroll
            for (int i = 0; i < 4; i++) a[i]  = Qs[(ty + i * 16) * ATT_STRIDE + d];
#pragma unroll
            for (int j = 0; j < 4; j++) bb[j] = Ks[(tx + j * 16) * ATT_STRIDE + d];
#pragma unroll
            for (int i = 0; i < 4; i++)
#pragma unroll
                for (int j = 0; j < 4; j++)
                    s[i][j] += a[i] * bb[j];
        }

#pragma unroll
        for (int i = 0; i < 4; i++) {
            float mx = s[i][0];
#pragma unroll
            for (int j = 1; j < 4; j++) mx = fmaxf(mx, s[i][j]);
#pragma unroll
            for (int m = 8; m > 0; m >>= 1)
                mx = fmaxf(mx, __shfl_xor_sync(0xffffffffu, mx, m));
            float m_new = fmaxf(m_run[i], mx);
            float corr  = __expf(m_run[i] - m_new);
            float psum  = 0.f;
#pragma unroll
            for (int j = 0; j < 4; j++) {
                s[i][j] = __expf(s[i][j] - m_new);
                psum += s[i][j];
            }
#pragma unroll
            for (int m = 8; m > 0; m >>= 1)
                psum += __shfl_xor_sync(0xffffffffu, psum, m);
            l_run[i] = l_run[i] * corr + psum;
            m_run[i] = m_new;
#pragma unroll
            for (int j = 0; j < 4; j++) acc_o[i][j] *= corr;
        }

#pragma unroll
        for (int i = 0; i < 4; i++)
#pragma unroll
            for (int j = 0; j < 4; j++)
                Ps[(ty + i * 16) * ATT_STRIDE + (tx + j * 16)] = s[i][j];
        __syncthreads();

#pragma unroll
        for (int kk = 0; kk < 64; kk++) {
            float a[4], bb[4];
#pragma unroll
            for (int i = 0; i < 4; i++) a[i]  = Ps[(ty + i * 16) * ATT_STRIDE + kk];
#pragma unroll
            for (int j = 0; j < 4; j++) bb[j] = Vs[kk * ATT_STRIDE + (tx + j * 16)];
#pragma unroll
            for (int i = 0; i < 4; i++)
#pragma unroll
                for (int j = 0; j < 4; j++)
                    acc_o[i][j] += a[i] * bb[j];
        }
        __syncthreads();
    }

#pragma unroll
    for (int i = 0; i < 4; i++) {
        int qr = ty + i * 16;
        float invl = 1.0f / l_run[i];
#pragma unroll
        for (int j = 0; j < 4; j++) {
            int dc = tx + j * 16;
            og[((size_t)(b * SS + q0 + qr)) * HID + h * HD + dc] = acc_o[i][j] * invl;
        }
    }
}

// ----------------------------------------------------------------------------
// Launch
// ----------------------------------------------------------------------------
extern "C" void kernel_launch(void* const* d_in, const int* in_sizes, int n_in,
                              void* d_out, int out_size)
{
    const float* x     = (const float*)d_in[0];
    const float* q_w   = (const float*)d_in[1];
    const float* q_b   = (const float*)d_in[2];
    const float* kv_w  = (const float*)d_in[3];
    const float* kv_b  = (const float*)d_in[4];
    const float* gq    = (const float*)d_in[5];
    const float* gk    = (const float*)d_in[6];
    const float* out_w = (const float*)d_in[7];
    float* out = (float*)d_out;

    float *pq, *pkv, *pao;
    cudaGetSymbolAddress((void**)&pq,  g_q);
    cudaGetSymbolAddress((void**)&pkv, g_kv);
    cudaGetSymbolAddress((void**)&pao, g_ao);

    cudaFuncSetAttribute(attn_kernel,
                         cudaFuncAttributeMaxDynamicSharedMemorySize, ATT_SMEM_BYTES);

    // Q projection: [8192,1024] = x @ q_w^T + q_b
    {
        dim3 grid(HID / 128, MR / 128);
        gemm_bf16x3<<<grid, 256>>>(x, q_w, q_b, pq, MR, HID, HID);
    }
    // KV projection: [8192,2048] = x @ kv_w^T + kv_b
    {
        dim3 grid((2 * HID) / 128, MR / 128);
        gemm_bf16x3<<<grid, 256>>>(x, kv_w, kv_b, pkv, MR, 2 * HID, HID);
    }
    // QK norm
    {
        int total_warps = 2 * MR * NH;
        int blocks = total_warps / 8;
        qknorm_kernel<<<blocks, 256>>>(gq, gk);
    }
    // Attention (fp32 SIMT)
    {
        dim3 grid(SS / 64, BB * NH);
        attn_kernel<<<grid, 256, ATT_SMEM_BYTES>>>(pq, pkv, pao);
    }
    // Output projection: out = ao @ out_w^T
    {
        dim3 grid(HID / 128, MR / 128);
        gemm_bf16x3<<<grid, 256>>>(pao, out_w, nullptr, out, MR, HID, HID);
    }
}

// round 4
// speedup vs baseline: 3.1238x; 2.0688x over previous
#include <cuda_runtime.h>
#include <cuda_bf16.h>
#include <math.h>
#include <stdint.h>

// Problem constants
#define BB   4
#define SS   2048
#define HID  1024
#define NH   16
#define HD   64
#define MR   (BB*SS)   // 8192 rows

// Scratch (device globals; no allocations allowed)
__device__ float g_q [ (size_t)MR * HID ];
__device__ float g_kv[ (size_t)MR * 2 * HID ];
__device__ float g_ao[ (size_t)MR * HID ];
// Pre-split bf16 operands for attention, layout [b][h][s][64]
__device__ __nv_bfloat16 g_qh[(size_t)MR * HID];
__device__ __nv_bfloat16 g_ql[(size_t)MR * HID];
__device__ __nv_bfloat16 g_kh[(size_t)MR * HID];
__device__ __nv_bfloat16 g_kl[(size_t)MR * HID];
__device__ __nv_bfloat16 g_vh[(size_t)MR * HID];
__device__ __nv_bfloat16 g_vl[(size_t)MR * HID];

__device__ __forceinline__ uint32_t smem_u32(const void* p) {
    uint32_t a;
    asm("{ .reg .u64 t; cvta.to.shared.u64 t, %1; cvt.u32.u64 %0, t; }"
        : "=r"(a) : "l"(p));
    return a;
}

__device__ __forceinline__ void bf16_split2(float x, float y,
                                            uint32_t& hi, uint32_t& lo) {
    __nv_bfloat16 hx = __float2bfloat16(x);
    __nv_bfloat16 hy = __float2bfloat16(y);
    __nv_bfloat16 lx = __float2bfloat16(x - __bfloat162float(hx));
    __nv_bfloat16 ly = __float2bfloat16(y - __bfloat162float(hy));
    __nv_bfloat162 h; h.x = hx; h.y = hy;
    __nv_bfloat162 l; l.x = lx; l.y = ly;
    hi = *reinterpret_cast<uint32_t*>(&h);
    lo = *reinterpret_cast<uint32_t*>(&l);
}

#define LDM_X4(r0, r1, r2, r3, addr) \
    asm volatile("ldmatrix.sync.aligned.m8n8.x4.shared.b16 {%0,%1,%2,%3}, [%4];" \
                 : "=r"(r0), "=r"(r1), "=r"(r2), "=r"(r3) : "r"(addr))
#define LDM_X4T(r0, r1, r2, r3, addr) \
    asm volatile("ldmatrix.sync.aligned.m8n8.x4.trans.shared.b16 {%0,%1,%2,%3}, [%4];" \
                 : "=r"(r0), "=r"(r1), "=r"(r2), "=r"(r3) : "r"(addr))

#define MMA_BF16(d, a, b0v, b1v) \
    asm volatile("mma.sync.aligned.m16n8k16.row.col.f32.bf16.bf16.f32 " \
                 "{%0,%1,%2,%3}, {%4,%5,%6,%7}, {%8,%9}, {%0,%1,%2,%3};" \
                 : "+f"((d)[0]), "+f"((d)[1]), "+f"((d)[2]), "+f"((d)[3]) \
                 : "r"((a)[0]), "r"((a)[1]), "r"((a)[2]), "r"((a)[3]), \
                   "r"(b0v), "r"(b1v))

#define CP_ASYNC16(dst, src) \
    asm volatile("cp.async.cg.shared.global [%0], [%1], 16;" \
                 :: "r"(dst), "l"(src) : "memory")
#define CP_COMMIT() asm volatile("cp.async.commit_group;" ::: "memory")
#define CP_WAIT1()  asm volatile("cp.async.wait_group 1;" ::: "memory")
#define CP_WAIT0()  asm volatile("cp.async.wait_group 0;" ::: "memory")

// ============================================================================
// 3xBF16 mma.sync GEMM (proven round-3 kernel, unchanged)
// ============================================================================
#define KC    32
#define PITCH 40

__global__ __launch_bounds__(256, 2)
void gemm_bf16x3(const float* __restrict__ A, const float* __restrict__ W,
                 const float* __restrict__ bias, float* __restrict__ C,
                 int M, int N, int K)
{
    __shared__ __align__(16) __nv_bfloat16 sAh[128 * PITCH];
    __shared__ __align__(16) __nv_bfloat16 sAl[128 * PITCH];
    __shared__ __align__(16) __nv_bfloat16 sBh[128 * PITCH];
    __shared__ __align__(16) __nv_bfloat16 sBl[128 * PITCH];

    const int tid  = threadIdx.x;
    const int wid  = tid >> 5;
    const int lane = tid & 31;
    const int row0 = blockIdx.y * 128;
    const int col0 = blockIdx.x * 128;
    const int wm   = (wid >> 2) * 64;
    const int wn   = (wid & 3) * 32;

    const uint32_t bAh = smem_u32(sAh);
    const uint32_t bAl = smem_u32(sAl);
    const uint32_t bBh = smem_u32(sBh);
    const uint32_t bBl = smem_u32(sBl);

    const int a_row = lane & 15;
    const int a_k   = (lane >> 4) << 3;
    const int b_n   = (lane & 7) + ((lane >> 4) << 3);
    const int b_k   = lane & 8;

    float acc[4][4][4];
#pragma unroll
    for (int mt = 0; mt < 4; mt++)
#pragma unroll
        for (int nt = 0; nt < 4; nt++)
#pragma unroll
            for (int r = 0; r < 4; r++) acc[mt][nt][r] = 0.f;

    for (int k0 = 0; k0 < K; k0 += KC) {
#pragma unroll
        for (int t = 0; t < 4; t++) {
            int idx = tid + t * 256;
            int r   = idx >> 3;
            int c4  = (idx & 7) * 4;
            float4 v = *reinterpret_cast<const float4*>(
                &A[(size_t)(row0 + r) * K + k0 + c4]);
            uint32_t h0, l0, h1, l1;
            bf16_split2(v.x, v.y, h0, l0);
            bf16_split2(v.z, v.w, h1, l1);
            *reinterpret_cast<uint2*>(&sAh[r * PITCH + c4]) = make_uint2(h0, h1);
            *reinterpret_cast<uint2*>(&sAl[r * PITCH + c4]) = make_uint2(l0, l1);
        }
#pragma unroll
        for (int t = 0; t < 4; t++) {
            int idx = tid + t * 256;
            int r   = idx >> 3;
            int c4  = (idx & 7) * 4;
            float4 v = *reinterpret_cast<const float4*>(
                &W[(size_t)(col0 + r) * K + k0 + c4]);
            uint32_t h0, l0, h1, l1;
            bf16_split2(v.x, v.y, h0, l0);
            bf16_split2(v.z, v.w, h1, l1);
            *reinterpret_cast<uint2*>(&sBh[r * PITCH + c4]) = make_uint2(h0, h1);
            *reinterpret_cast<uint2*>(&sBl[r * PITCH + c4]) = make_uint2(l0, l1);
        }
        __syncthreads();

#pragma unroll
        for (int kk = 0; kk < KC; kk += 16) {
            uint32_t bh[8], bl[8];
#pragma unroll
            for (int p = 0; p < 2; p++) {
                uint32_t off = (uint32_t)((wn + p * 16 + b_n) * PITCH + kk + b_k) * 2u;
                LDM_X4(bh[p*4+0], bh[p*4+1], bh[p*4+2], bh[p*4+3], bBh + off);
                LDM_X4(bl[p*4+0], bl[p*4+1], bl[p*4+2], bl[p*4+3], bBl + off);
            }
#pragma unroll
            for (int mt = 0; mt < 4; mt++) {
                uint32_t ah[4], al[4];
                uint32_t off = (uint32_t)((wm + mt * 16 + a_row) * PITCH + kk + a_k) * 2u;
                LDM_X4(ah[0], ah[1], ah[2], ah[3], bAh + off);
                LDM_X4(al[0], al[1], al[2], al[3], bAl + off);
#pragma unroll
                for (int nt = 0; nt < 4; nt++) {
                    int p = nt >> 1;
                    int o = (nt & 1) * 2;
                    MMA_BF16(acc[mt][nt], ah, bh[p*4+o], bh[p*4+o+1]);
                    MMA_BF16(acc[mt][nt], ah, bl[p*4+o], bl[p*4+o+1]);
                    MMA_BF16(acc[mt][nt], al, bh[p*4+o], bh[p*4+o+1]);
                }
            }
        }
        __syncthreads();
    }

    const int g  = lane >> 2;
    const int t2 = (lane & 3) * 2;
#pragma unroll
    for (int mt = 0; mt < 4; mt++) {
#pragma unroll
        for (int nt = 0; nt < 4; nt++) {
            int row = row0 + wm + mt * 16 + g;
            int col = col0 + wn + nt * 8 + t2;
            float bv0 = bias ? __ldg(&bias[col])     : 0.f;
            float bv1 = bias ? __ldg(&bias[col + 1]) : 0.f;
            *reinterpret_cast<float2*>(&C[(size_t)row * N + col]) =
                make_float2(acc[mt][nt][0] + bv0, acc[mt][nt][1] + bv1);
            *reinterpret_cast<float2*>(&C[(size_t)(row + 8) * N + col]) =
                make_float2(acc[mt][nt][2] + bv0, acc[mt][nt][3] + bv1);
        }
    }
}

// ============================================================================
// QK-norm + hi/lo bf16 split + head-major relayout (q, k, v)
// One warp per (row, head, type). Output [b][h][s][64].
// ============================================================================
__global__ __launch_bounds__(256)
void qknorm_split(const float* __restrict__ gq_gamma,
                  const float* __restrict__ gk_gamma)
{
    int warp = (blockIdx.x * blockDim.x + threadIdx.x) >> 5;
    int lane = threadIdx.x & 31;
    const int per = MR * NH;
    int seg = warp / per;
    int t   = warp - seg * per;
    int row = t >> 4;
    int h   = t & 15;
    int b   = row / SS;
    int s   = row - b * SS;

    const float* src;
    bool donorm = true;
    const float* gamma = gq_gamma;
    __nv_bfloat16 *dh, *dl;
    if (seg == 0) {
        src = g_q + (size_t)row * HID + h * HD;
        dh = g_qh; dl = g_ql;
    } else if (seg == 1) {
        src = g_kv + (size_t)row * (2 * HID) + h * HD;
        gamma = gk_gamma;
        dh = g_kh; dl = g_kl;
    } else {
        src = g_kv + (size_t)row * (2 * HID) + HID + h * HD;
        donorm = false;
        dh = g_vh; dl = g_vl;
    }

    float2 v = *reinterpret_cast<const float2*>(src + lane * 2);
    if (donorm) {
        float ss = v.x * v.x + v.y * v.y;
#pragma unroll
        for (int m = 16; m > 0; m >>= 1)
            ss += __shfl_xor_sync(0xffffffffu, ss, m);
        float inv = 8.0f / fmaxf(sqrtf(ss), 1e-12f);
        float2 g = *reinterpret_cast<const float2*>(gamma + h * HD + lane * 2);
        v.x *= inv * g.x;
        v.y *= inv * g.y;
    }
    uint32_t hi, lo;
    bf16_split2(v.x, v.y, hi, lo);
    size_t out = ((size_t)(b * NH + h) * SS + s) * HD + lane * 2;
    *reinterpret_cast<uint32_t*>(dh + out) = hi;
    *reinterpret_cast<uint32_t*>(dl + out) = lo;
}

// ============================================================================
// Tensor-core flash attention (3xbf16 QK and PV), cp.async double-buffered.
// CTA: 128 queries x one (b,h); 8 warps x 16 rows; KV tile = 64 keys.
// ============================================================================
#define APITCH 72
#define QTILE_EL  (128 * APITCH)
#define KVARR_EL  (64 * APITCH)
#define BUF_EL    (4 * KVARR_EL)
#define ATT_SMEM  ((2 * QTILE_EL + 2 * BUF_EL) * 2)   // 110592 bytes
#define NT        (SS / 64)                            // 32

__global__ __launch_bounds__(256, 1)
void attn_mma(const __nv_bfloat16* __restrict__ qh, const __nv_bfloat16* __restrict__ ql,
              const __nv_bfloat16* __restrict__ kh, const __nv_bfloat16* __restrict__ kl,
              const __nv_bfloat16* __restrict__ vh, const __nv_bfloat16* __restrict__ vl,
              float* __restrict__ og)
{
    extern __shared__ __nv_bfloat16 sm[];
    __nv_bfloat16* Qh = sm;
    __nv_bfloat16* Ql = Qh + QTILE_EL;
    __nv_bfloat16* Bf = Ql + QTILE_EL;   // 2 x [Kh|Kl|Vh|Vl] of 64x72

    const int tid  = threadIdx.x;
    const int wid  = tid >> 5;
    const int lane = tid & 31;
    const int bh   = blockIdx.y;
    const int q0   = blockIdx.x * 128;
    const int wm   = wid * 16;
    const size_t bh_off = (size_t)bh * SS * HD;

    const __nv_bfloat16* srcs[4] = {kh + bh_off, kl + bh_off, vh + bh_off, vl + bh_off};
    const uint32_t buf_u[2] = { smem_u32(Bf), smem_u32(Bf + BUF_EL) };
    const uint32_t Qh_u = smem_u32(Qh);
    const uint32_t Ql_u = smem_u32(Ql);

    // ---- issue KV tile loads (cp.async) ----
    auto issue = [&](int kt, int bsel) {
#pragma unroll
        for (int i = 0; i < 8; i++) {
            const __nv_bfloat16* sp = srcs[i >> 1];
            int rem = ((i & 1) << 8) + tid;
            int r = rem >> 3;
            int c = (rem & 7) * 8;
            uint32_t dst = buf_u[bsel] + (uint32_t)((i >> 1) * KVARR_EL + r * APITCH + c) * 2u;
            CP_ASYNC16(dst, sp + (size_t)(kt * 64 + r) * HD + c);
        }
        CP_COMMIT();
    };

    issue(0, 0);
    issue(1, 1);

    // ---- load Q tile (hi/lo) into smem ----
    {
        const __nv_bfloat16* qsrc[2] = {qh + bh_off, ql + bh_off};
        __nv_bfloat16* qdst[2] = {Qh, Ql};
#pragma unroll
        for (int i = 0; i < 8; i++) {
            int rem = ((i & 3) << 8) + tid;
            int r = rem >> 3;
            int c = (rem & 7) * 8;
            uint4 v = *reinterpret_cast<const uint4*>(
                qsrc[i >> 2] + (size_t)(q0 + r) * HD + c);
            *reinterpret_cast<uint4*>(qdst[i >> 2] + r * APITCH + c) = v;
        }
    }
    __syncthreads();

    // ---- hoist Q fragments ----
    const int a_row = lane & 15;
    const int a_k   = (lane >> 4) << 3;
    uint32_t qfh[4][4], qfl[4][4];
#pragma unroll
    for (int ks = 0; ks < 4; ks++) {
        uint32_t off = (uint32_t)((wm + a_row) * APITCH + ks * 16 + a_k) * 2u;
        LDM_X4(qfh[ks][0], qfh[ks][1], qfh[ks][2], qfh[ks][3], Qh_u + off);
        LDM_X4(qfl[ks][0], qfl[ks][1], qfl[ks][2], qfl[ks][3], Ql_u + off);
    }

    const int b_n = (lane & 7) + ((lane >> 4) << 3);
    const int b_k = lane & 8;

    float m0 = -1e30f, m1 = -1e30f, l0 = 0.f, l1 = 0.f;
    float O[8][4];
#pragma unroll
    for (int d = 0; d < 8; d++)
#pragma unroll
        for (int r = 0; r < 4; r++) O[d][r] = 0.f;

    for (int t = 0; t < NT; t++) {
        if (t < NT - 1) { CP_WAIT1(); } else { CP_WAIT0(); }
        __syncthreads();

        const uint32_t Ks_h = buf_u[t & 1];
        const uint32_t Ks_l = Ks_h + KVARR_EL * 2u;
        const uint32_t Vs_h = Ks_h + 2u * KVARR_EL * 2u;
        const uint32_t Vs_l = Ks_h + 3u * KVARR_EL * 2u;

        // ---- S = Q K^T (3-term) ----
        float S[8][4];
#pragma unroll
        for (int nt = 0; nt < 8; nt++)
#pragma unroll
            for (int r = 0; r < 4; r++) S[nt][r] = 0.f;

#pragma unroll
        for (int ks = 0; ks < 4; ks++) {
            uint32_t kfh[4][4], kfl[4][4];
#pragma unroll
            for (int p = 0; p < 4; p++) {
                uint32_t off = (uint32_t)((p * 16 + b_n) * APITCH + ks * 16 + b_k) * 2u;
                LDM_X4(kfh[p][0], kfh[p][1], kfh[p][2], kfh[p][3], Ks_h + off);
                LDM_X4(kfl[p][0], kfl[p][1], kfl[p][2], kfl[p][3], Ks_l + off);
            }
#pragma unroll
            for (int nt = 0; nt < 8; nt++) {
                int p = nt >> 1;
                int o = (nt & 1) * 2;
                MMA_BF16(S[nt], qfh[ks], kfh[p][o], kfh[p][o+1]);
                MMA_BF16(S[nt], qfh[ks], kfl[p][o], kfl[p][o+1]);
                MMA_BF16(S[nt], qfl[ks], kfh[p][o], kfh[p][o+1]);
            }
        }

        // ---- online softmax (rows g, g+8 within warp quad) ----
        float mx0 = -1e30f, mx1 = -1e30f;
#pragma unroll
        for (int nt = 0; nt < 8; nt++) {
            mx0 = fmaxf(mx0, fmaxf(S[nt][0], S[nt][1]));
            mx1 = fmaxf(mx1, fmaxf(S[nt][2], S[nt][3]));
        }
        mx0 = fmaxf(mx0, __shfl_xor_sync(0xffffffffu, mx0, 1));
        mx0 = fmaxf(mx0, __shfl_xor_sync(0xffffffffu, mx0, 2));
        mx1 = fmaxf(mx1, __shfl_xor_sync(0xffffffffu, mx1, 1));
        mx1 = fmaxf(mx1, __shfl_xor_sync(0xffffffffu, mx1, 2));
        float mn0 = fmaxf(m0, mx0), mn1 = fmaxf(m1, mx1);
        float c0 = __expf(m0 - mn0), c1 = __expf(m1 - mn1);
        m0 = mn0; m1 = mn1;

        float s0 = 0.f, s1 = 0.f;
#pragma unroll
        for (int nt = 0; nt < 8; nt++) {
            S[nt][0] = __expf(S[nt][0] - m0);
            S[nt][1] = __expf(S[nt][1] - m0);
            S[nt][2] = __expf(S[nt][2] - m1);
            S[nt][3] = __expf(S[nt][3] - m1);
            s0 += S[nt][0] + S[nt][1];
            s1 += S[nt][2] + S[nt][3];
        }
        s0 += __shfl_xor_sync(0xffffffffu, s0, 1);
        s0 += __shfl_xor_sync(0xffffffffu, s0, 2);
        s1 += __shfl_xor_sync(0xffffffffu, s1, 1);
        s1 += __shfl_xor_sync(0xffffffffu, s1, 2);
        l0 = l0 * c0 + s0;
        l1 = l1 * c1 + s1;
#pragma unroll
        for (int d = 0; d < 8; d++) {
            O[d][0] *= c0; O[d][1] *= c0;
            O[d][2] *= c1; O[d][3] *= c1;
        }

        // ---- P fragments (hi/lo) ----
        uint32_t pfh[4][4], pfl[4][4];
#pragma unroll
        for (int ks = 0; ks < 4; ks++) {
            bf16_split2(S[2*ks][0],   S[2*ks][1],   pfh[ks][0], pfl[ks][0]);
            bf16_split2(S[2*ks][2],   S[2*ks][3],   pfh[ks][1], pfl[ks][1]);
            bf16_split2(S[2*ks+1][0], S[2*ks+1][1], pfh[ks][2], pfl[ks][2]);
            bf16_split2(S[2*ks+1][2], S[2*ks+1][3], pfh[ks][3], pfl[ks][3]);
        }

        // ---- O += P V (3-term) ----
#pragma unroll
        for (int ks = 0; ks < 4; ks++) {
            uint32_t vfh[4][4], vfl[4][4];
#pragma unroll
            for (int pd = 0; pd < 4; pd++) {
                uint32_t off = (uint32_t)((ks * 16 + (lane & 15)) * APITCH +
                                          pd * 16 + ((lane >> 4) << 3)) * 2u;
                LDM_X4T(vfh[pd][0], vfh[pd][1], vfh[pd][2], vfh[pd][3], Vs_h + off);
                LDM_X4T(vfl[pd][0], vfl[pd][1], vfl[pd][2], vfl[pd][3], Vs_l + off);
            }
#pragma unroll
            for (int dt = 0; dt < 8; dt++) {
                int pd = dt >> 1;
                int o  = (dt & 1) * 2;
                MMA_BF16(O[dt], pfh[ks], vfh[pd][o], vfh[pd][o+1]);
                MMA_BF16(O[dt], pfh[ks], vfl[pd][o], vfl[pd][o+1]);
                MMA_BF16(O[dt], pfl[ks], vfh[pd][o], vfh[pd][o+1]);
            }
        }

        __syncthreads();
        if (t + 2 < NT) issue(t + 2, t & 1);
    }

    // ---- epilogue: O / l -> g_ao [b][s][h*64+d] ----
    const int g  = lane >> 2;
    const int t2 = (lane & 3) * 2;
    const int b  = bh >> 4;
    const int h  = bh & 15;
    float inv0 = 1.0f / l0, inv1 = 1.0f / l1;
    int row = b * SS + q0 + wm + g;
#pragma unroll
    for (int dt = 0; dt < 8; dt++) {
        int col = h * HD + dt * 8 + t2;
        *reinterpret_cast<float2*>(&og[(size_t)row * HID + col]) =
            make_float2(O[dt][0] * inv0, O[dt][1] * inv0);
        *reinterpret_cast<float2*>(&og[(size_t)(row + 8) * HID + col]) =
            make_float2(O[dt][2] * inv1, O[dt][3] * inv1);
    }
}

// ----------------------------------------------------------------------------
// Launch
// ----------------------------------------------------------------------------
extern "C" void kernel_launch(void* const* d_in, const int* in_sizes, int n_in,
                              void* d_out, int out_size)
{
    const float* x     = (const float*)d_in[0];
    const float* q_w   = (const float*)d_in[1];
    const float* q_b   = (const float*)d_in[2];
    const float* kv_w  = (const float*)d_in[3];
    const float* kv_b  = (const float*)d_in[4];
    const float* gq    = (const float*)d_in[5];
    const float* gk    = (const float*)d_in[6];
    const float* out_w = (const float*)d_in[7];
    float* out = (float*)d_out;

    float *pq, *pkv, *pao;
    cudaGetSymbolAddress((void**)&pq,  g_q);
    cudaGetSymbolAddress((void**)&pkv, g_kv);
    cudaGetSymbolAddress((void**)&pao, g_ao);
    __nv_bfloat16 *pqh, *pql, *pkh, *pkl, *pvh, *pvl;
    cudaGetSymbolAddress((void**)&pqh, g_qh);
    cudaGetSymbolAddress((void**)&pql, g_ql);
    cudaGetSymbolAddress((void**)&pkh, g_kh);
    cudaGetSymbolAddress((void**)&pkl, g_kl);
    cudaGetSymbolAddress((void**)&pvh, g_vh);
    cudaGetSymbolAddress((void**)&pvl, g_vl);

    cudaFuncSetAttribute(attn_mma,
                         cudaFuncAttributeMaxDynamicSharedMemorySize, ATT_SMEM);

    // Q projection
    {
        dim3 grid(HID / 128, MR / 128);
        gemm_bf16x3<<<grid, 256>>>(x, q_w, q_b, pq, MR, HID, HID);
    }
    // KV projection
    {
        dim3 grid((2 * HID) / 128, MR / 128);
        gemm_bf16x3<<<grid, 256>>>(x, kv_w, kv_b, pkv, MR, 2 * HID, HID);
    }
    // QK norm + split + relayout
    {
        int total_warps = 3 * MR * NH;
        qknorm_split<<<total_warps / 8, 256>>>(gq, gk);
    }
    // Attention (tensor cores)
    {
        dim3 grid(SS / 128, BB * NH);   // (16, 64)
        attn_mma<<<grid, 256, ATT_SMEM>>>(pqh, pql, pkh, pkl, pvh, pvl, pao);
    }
    // Output projection
    {
        dim3 grid(HID / 128, MR / 128);
        gemm_bf16x3<<<grid, 256>>>(pao, out_w, nullptr, out, MR, HID, HID);
    }
}